// round 1
// baseline (speedup 1.0000x reference)
#include <cuda_runtime.h>

#define S_LEN  4096
#define BATCH  2
#define DMODEL 768
#define NHEAD  12
#define HDIM   64
#define WSZ    256
#define NROWS  (S_LEN * BATCH)   // 8192

// Scratch for projected q/k/v (static device globals: allowed, no allocation)
__device__ float g_q[(size_t)NROWS * DMODEL];
__device__ float g_k[(size_t)NROWS * DMODEL];
__device__ float g_v[(size_t)NROWS * DMODEL];

// ---------------------------------------------------------------------------
// Kernel 1: fused QKV projection.  C = val @ W + b  (q additionally * 0.125)
// val: (8192, 768) row-major, W: (768, 768) row-major, per-z select q/k/v.
// Classic 128x128x16 fp32 SIMT tile, 256 threads, 8x8 per-thread microtile.
// ---------------------------------------------------------------------------
#define BM 128
#define BN 128
#define BK 16

__global__ __launch_bounds__(256) void qkv_gemm(
    const float* __restrict__ val,
    const float* __restrict__ Wq, const float* __restrict__ bq,
    const float* __restrict__ Wk, const float* __restrict__ bk,
    const float* __restrict__ Wv, const float* __restrict__ bv)
{
    const int z = blockIdx.z;
    const float* __restrict__ W    = (z == 0) ? Wq : (z == 1) ? Wk : Wv;
    const float* __restrict__ bias = (z == 0) ? bq : (z == 1) ? bk : bv;
    float* outp = (z == 0) ? g_q : (z == 1) ? g_k : g_v;
    const float scale = (z == 0) ? 0.125f : 1.0f;   // 1/sqrt(64)

    __shared__ float As[BK][BM + 4];   // A stored transposed: As[k][m]
    __shared__ float Bs[BK][BN];

    const int tid = threadIdx.x;
    const int bm = blockIdx.y * BM;
    const int bn = blockIdx.x * BN;
    const int tx = tid & 15;    // n direction
    const int ty = tid >> 4;    // m direction

    float acc[8][8];
#pragma unroll
    for (int i = 0; i < 8; i++)
#pragma unroll
        for (int j = 0; j < 8; j++) acc[i][j] = 0.f;

    // A-load mapping: tid -> (row 0..63, k-quad), two passes cover 128 rows
    const int row_a = tid >> 2;
    const int ka4   = (tid & 3) << 2;
    // B-load mapping: 16 rows x 32 float4, two passes
    const int rb = tid >> 5;            // 0..7
    const int cb = (tid & 31) << 2;

    for (int k0 = 0; k0 < DMODEL; k0 += BK) {
#pragma unroll
        for (int h = 0; h < 2; h++) {
            int r = row_a + h * 64;
            float4 a = *(const float4*)(val + (size_t)(bm + r) * DMODEL + k0 + ka4);
            As[ka4 + 0][r] = a.x; As[ka4 + 1][r] = a.y;
            As[ka4 + 2][r] = a.z; As[ka4 + 3][r] = a.w;
        }
#pragma unroll
        for (int h = 0; h < 2; h++) {
            int rr = rb + h * 8;
            *(float4*)(&Bs[rr][cb]) =
                *(const float4*)(W + (size_t)(k0 + rr) * DMODEL + bn + cb);
        }
        __syncthreads();

#pragma unroll
        for (int kk = 0; kk < BK; kk++) {
            float a[8], b[8];
            *(float4*)&a[0] = *(const float4*)&As[kk][ty * 8];
            *(float4*)&a[4] = *(const float4*)&As[kk][ty * 8 + 4];
            *(float4*)&b[0] = *(const float4*)&Bs[kk][tx * 8];
            *(float4*)&b[4] = *(const float4*)&Bs[kk][tx * 8 + 4];
#pragma unroll
            for (int i = 0; i < 8; i++)
#pragma unroll
                for (int j = 0; j < 8; j++)
                    acc[i][j] += a[i] * b[j];
        }
        __syncthreads();
    }

    float bb[8];
    *(float4*)&bb[0] = *(const float4*)(bias + bn + tx * 8);
    *(float4*)&bb[4] = *(const float4*)(bias + bn + tx * 8 + 4);

#pragma unroll
    for (int i = 0; i < 8; i++) {
        int r = bm + ty * 8 + i;
        float4 o0, o1;
        o0.x = (acc[i][0] + bb[0]) * scale;
        o0.y = (acc[i][1] + bb[1]) * scale;
        o0.z = (acc[i][2] + bb[2]) * scale;
        o0.w = (acc[i][3] + bb[3]) * scale;
        o1.x = (acc[i][4] + bb[4]) * scale;
        o1.y = (acc[i][5] + bb[5]) * scale;
        o1.z = (acc[i][6] + bb[6]) * scale;
        o1.w = (acc[i][7] + bb[7]) * scale;
        *(float4*)(outp + (size_t)r * DMODEL + bn + tx * 8)     = o0;
        *(float4*)(outp + (size_t)r * DMODEL + bn + tx * 8 + 4) = o1;
    }
}

// ---------------------------------------------------------------------------
// Kernel 2: causal sliding-window attention.
// One thread owns one query row (q + acc fully in registers, 128 floats).
// Keys j in [i-256, i].  Block = 128 consecutive queries of one (b,h).
// K/V staged in shared in 64-key tiles; warp-uniform skip of dead keys.
// ---------------------------------------------------------------------------
#define KTILE 64

__global__ __launch_bounds__(128) void attn_kernel(float* __restrict__ out)
{
    __shared__ float Ks[KTILE][HDIM];
    __shared__ float Vs[KTILE][HDIM];

    const int chunk = blockIdx.x;      // 0..31 (128 queries each)
    const int h     = blockIdx.y;      // 0..11
    const int b     = blockIdx.z;      // 0..1
    const int tid   = threadIdx.x;
    const int i     = chunk * 128 + tid;          // absolute query index
    const int wb    = chunk * 128 + (tid & ~31);  // warp-uniform query base

    // load q row into registers
    float q[HDIM];
    {
        const float4* qg =
            (const float4*)(g_q + ((size_t)i * BATCH + b) * DMODEL + h * HDIM);
#pragma unroll
        for (int d4 = 0; d4 < 16; d4++) {
            float4 t = qg[d4];
            q[4 * d4 + 0] = t.x; q[4 * d4 + 1] = t.y;
            q[4 * d4 + 2] = t.z; q[4 * d4 + 3] = t.w;
        }
    }

    float acc[HDIM];
#pragma unroll
    for (int d = 0; d < HDIM; d++) acc[d] = 0.f;
    float m = -1e30f, l = 0.f;

    const int jstart = chunk * 128 - WSZ;   // 384-key span, 6 tiles of 64

    for (int t = 0; t < 6; t++) {
        const int j0 = jstart + t * KTILE;
        __syncthreads();
        // cooperative load of K/V tile (zero-fill out-of-range rows)
#pragma unroll
        for (int it = 0; it < 8; it++) {
            int f   = tid + 128 * it;
            int row = f >> 4;
            int c4  = (f & 15) << 2;
            int j   = j0 + row;
            float4 kk4 = make_float4(0.f, 0.f, 0.f, 0.f);
            float4 vv4 = make_float4(0.f, 0.f, 0.f, 0.f);
            if (j >= 0 && j < S_LEN) {
                size_t base = ((size_t)j * BATCH + b) * DMODEL + h * HDIM + c4;
                kk4 = *(const float4*)(g_k + base);
                vv4 = *(const float4*)(g_v + base);
            }
            *(float4*)&Ks[row][c4] = kk4;
            *(float4*)&Vs[row][c4] = vv4;
        }
        __syncthreads();

        for (int jj = 0; jj < KTILE; jj++) {
            const int j = j0 + jj;
            // warp-uniform skip: key dead for every lane in this warp
            if (j < 0)            continue;
            if (j > wb + 31)      continue;
            if (j < wb - WSZ)     continue;

            float s = 0.f;
            const float4* kr = (const float4*)&Ks[jj][0];
#pragma unroll
            for (int d4 = 0; d4 < 16; d4++) {
                float4 kv = kr[d4];
                s += q[4 * d4 + 0] * kv.x + q[4 * d4 + 1] * kv.y
                   + q[4 * d4 + 2] * kv.z + q[4 * d4 + 3] * kv.w;
            }

            if (j <= i && j >= i - WSZ) {
                if (s > m) {                      // lazy rescale (exact)
                    float sc = __expf(m - s);
                    m = s;
                    l *= sc;
#pragma unroll
                    for (int d = 0; d < HDIM; d++) acc[d] *= sc;
                }
                float p = __expf(s - m);
                l += p;
                const float4* vr = (const float4*)&Vs[jj][0];
#pragma unroll
                for (int d4 = 0; d4 < 16; d4++) {
                    float4 vv = vr[d4];
                    acc[4 * d4 + 0] += p * vv.x;
                    acc[4 * d4 + 1] += p * vv.y;
                    acc[4 * d4 + 2] += p * vv.z;
                    acc[4 * d4 + 3] += p * vv.w;
                }
            }
        }
    }

    const float inv = 1.f / l;
    float4* og = (float4*)(out + ((size_t)i * BATCH + b) * DMODEL + h * HDIM);
#pragma unroll
    for (int d4 = 0; d4 < 16; d4++) {
        og[d4] = make_float4(acc[4 * d4 + 0] * inv, acc[4 * d4 + 1] * inv,
                             acc[4 * d4 + 2] * inv, acc[4 * d4 + 3] * inv);
    }
}

// ---------------------------------------------------------------------------
extern "C" void kernel_launch(void* const* d_in, const int* in_sizes, int n_in,
                              void* d_out, int out_size)
{
    const float* val = (const float*)d_in[0];
    const float* Wq  = (const float*)d_in[1];
    const float* bq  = (const float*)d_in[2];
    const float* Wk  = (const float*)d_in[3];
    const float* bk  = (const float*)d_in[4];
    const float* Wv  = (const float*)d_in[5];
    const float* bv  = (const float*)d_in[6];
    float* out = (float*)d_out;

    dim3 g1(DMODEL / BN, NROWS / BM, 3);   // 6 x 64 x 3 blocks
    qkv_gemm<<<g1, 256>>>(val, Wq, bq, Wk, bk, Wv, bv);

    dim3 g2(S_LEN / 128, NHEAD, BATCH);    // 32 x 12 x 2 blocks
    attn_kernel<<<g2, 128>>>(out);
}

// round 2
// speedup vs baseline: 1.6106x; 1.6106x over previous
#include <cuda_runtime.h>
#include <cstdint>

#define S_LEN  4096
#define BATCH  2
#define DMODEL 768
#define NHEAD  12
#define HDIM   64
#define WSZ    256
#define NROWS  (S_LEN * BATCH)   // 8192

__device__ float g_q[(size_t)NROWS * DMODEL];
__device__ float g_k[(size_t)NROWS * DMODEL];
__device__ float g_v[(size_t)NROWS * DMODEL];

// ---------------------------------------------------------------------------
// helpers: packed f32x2 and tf32 conversion
// ---------------------------------------------------------------------------
__device__ __forceinline__ unsigned long long pk2(float x, float y) {
    unsigned long long r;
    asm("mov.b64 %0,{%1,%2};" : "=l"(r) : "f"(x), "f"(y));
    return r;
}
__device__ __forceinline__ void upk2(unsigned long long v, float& x, float& y) {
    asm("mov.b64 {%0,%1},%2;" : "=f"(x), "=f"(y) : "l"(v));
}
__device__ __forceinline__ unsigned long long fma2_(unsigned long long a,
                                                    unsigned long long b,
                                                    unsigned long long c) {
    unsigned long long d;
    asm("fma.rn.f32x2 %0,%1,%2,%3;" : "=l"(d) : "l"(a), "l"(b), "l"(c));
    return d;
}
__device__ __forceinline__ unsigned long long mul2_(unsigned long long a,
                                                    unsigned long long b) {
    unsigned long long d;
    asm("mul.rn.f32x2 %0,%1,%2;" : "=l"(d) : "l"(a), "l"(b));
    return d;
}
__device__ __forceinline__ uint32_t tf32r(float x) {
    uint32_t u;
    asm("cvt.rna.tf32.f32 %0,%1;" : "=r"(u) : "f"(x));
    return u;
}

// ---------------------------------------------------------------------------
// Kernel 1: fused QKV projection using tf32 tensor cores (mma.m16n8k8).
// C(8192x768) = val(8192x768) @ W(768x768) + b   (q also * 0.125)
// Block: 128x128 tile, 128 threads = 4 warps, warp tile 64x64.
// Double-buffered smem, register prefetch of next k-tile.
// ---------------------------------------------------------------------------
#define GBM 128
#define GBN 128
#define GBK 16
#define KTILES (DMODEL / GBK)   // 48

__device__ __forceinline__ void mma_tf32(float c[4], const uint32_t a[4],
                                         const uint32_t b[2]) {
    asm volatile(
        "mma.sync.aligned.m16n8k8.row.col.f32.tf32.tf32.f32 "
        "{%0,%1,%2,%3},{%4,%5,%6,%7},{%8,%9},{%0,%1,%2,%3};"
        : "+f"(c[0]), "+f"(c[1]), "+f"(c[2]), "+f"(c[3])
        : "r"(a[0]), "r"(a[1]), "r"(a[2]), "r"(a[3]), "r"(b[0]), "r"(b[1]));
}

__global__ __launch_bounds__(128) void qkv_gemm_tc(
    const float* __restrict__ val,
    const float* __restrict__ Wq, const float* __restrict__ bq,
    const float* __restrict__ Wk, const float* __restrict__ bk,
    const float* __restrict__ Wv, const float* __restrict__ bv)
{
    const int z = blockIdx.z;
    const float* __restrict__ W    = (z == 0) ? Wq : (z == 1) ? Wk : Wv;
    const float* __restrict__ bias = (z == 0) ? bq : (z == 1) ? bk : bv;
    float* outp = (z == 0) ? g_q : (z == 1) ? g_k : g_v;
    const float scale = (z == 0) ? 0.125f : 1.0f;

    __shared__ uint32_t As[2][GBM][20];    // padded: conflict-free a-frag loads
    __shared__ uint32_t Bs[2][GBK][136];   // padded: conflict-free b-frag loads

    const int tid  = threadIdx.x;
    const int lane = tid & 31;
    const int w    = tid >> 5;
    const int wm   = (w & 1) * 64;
    const int wn   = (w >> 1) * 64;
    const int bm   = blockIdx.y * GBM;
    const int bn   = blockIdx.x * GBN;

    const int brow = tid >> 3;          // 0..15
    const int bcol = (tid & 7) * 16;    // 0..112

    float acc[4][8][4];
#pragma unroll
    for (int mt = 0; mt < 4; mt++)
#pragma unroll
        for (int nt = 0; nt < 8; nt++)
#pragma unroll
            for (int i = 0; i < 4; i++) acc[mt][nt][i] = 0.f;

    float4 ar[4], br[4];

    // prefetch k-tile 0
#pragma unroll
    for (int i = 0; i < 4; i++)
        ar[i] = *(const float4*)(val + (size_t)(bm + tid) * DMODEL + i * 4);
#pragma unroll
    for (int i = 0; i < 4; i++)
        br[i] = *(const float4*)(W + (size_t)brow * DMODEL + bn + bcol + i * 4);

    // store tile 0 (with tf32 rounding)
#pragma unroll
    for (int i = 0; i < 4; i++) {
        uint4 u = make_uint4(tf32r(ar[i].x), tf32r(ar[i].y),
                             tf32r(ar[i].z), tf32r(ar[i].w));
        *(uint4*)&As[0][tid][i * 4] = u;
        uint4 v = make_uint4(tf32r(br[i].x), tf32r(br[i].y),
                             tf32r(br[i].z), tf32r(br[i].w));
        *(uint4*)&Bs[0][brow][bcol + i * 4] = v;
    }
    __syncthreads();

    for (int kt = 0; kt < KTILES; kt++) {
        const int buf = kt & 1;
        if (kt < KTILES - 1) {
            const int k0 = (kt + 1) * GBK;
#pragma unroll
            for (int i = 0; i < 4; i++)
                ar[i] = *(const float4*)(val + (size_t)(bm + tid) * DMODEL + k0 + i * 4);
#pragma unroll
            for (int i = 0; i < 4; i++)
                br[i] = *(const float4*)(W + (size_t)(k0 + brow) * DMODEL + bn + bcol + i * 4);
        }

#pragma unroll
        for (int ks = 0; ks < 2; ks++) {
            uint32_t af[4][4];
#pragma unroll
            for (int mt = 0; mt < 4; mt++) {
                const int r  = wm + mt * 16 + (lane >> 2);
                const int kc = ks * 8 + (lane & 3);
                af[mt][0] = As[buf][r][kc];
                af[mt][1] = As[buf][r + 8][kc];
                af[mt][2] = As[buf][r][kc + 4];
                af[mt][3] = As[buf][r + 8][kc + 4];
            }
            uint32_t bf[8][2];
#pragma unroll
            for (int nt = 0; nt < 8; nt++) {
                const int c  = wn + nt * 8 + (lane >> 2);
                const int kr = ks * 8 + (lane & 3);
                bf[nt][0] = Bs[buf][kr][c];
                bf[nt][1] = Bs[buf][kr + 4][c];
            }
#pragma unroll
            for (int mt = 0; mt < 4; mt++)
#pragma unroll
                for (int nt = 0; nt < 8; nt++)
                    mma_tf32(acc[mt][nt], af[mt], bf[nt]);
        }

        if (kt < KTILES - 1) {
            const int nb = buf ^ 1;
#pragma unroll
            for (int i = 0; i < 4; i++) {
                uint4 u = make_uint4(tf32r(ar[i].x), tf32r(ar[i].y),
                                     tf32r(ar[i].z), tf32r(ar[i].w));
                *(uint4*)&As[nb][tid][i * 4] = u;
                uint4 v = make_uint4(tf32r(br[i].x), tf32r(br[i].y),
                                     tf32r(br[i].z), tf32r(br[i].w));
                *(uint4*)&Bs[nb][brow][bcol + i * 4] = v;
            }
            __syncthreads();
        }
    }

    // epilogue: bias + scale, float2 stores
#pragma unroll
    for (int mt = 0; mt < 4; mt++) {
        const int row0 = bm + wm + mt * 16 + (lane >> 2);
#pragma unroll
        for (int nt = 0; nt < 8; nt++) {
            const int col = bn + wn + nt * 8 + 2 * (lane & 3);
            const float2 b2 = *(const float2*)(bias + col);
            float2 o0, o1;
            o0.x = (acc[mt][nt][0] + b2.x) * scale;
            o0.y = (acc[mt][nt][1] + b2.y) * scale;
            o1.x = (acc[mt][nt][2] + b2.x) * scale;
            o1.y = (acc[mt][nt][3] + b2.y) * scale;
            *(float2*)(outp + (size_t)row0 * DMODEL + col)       = o0;
            *(float2*)(outp + (size_t)(row0 + 8) * DMODEL + col) = o1;
        }
    }
}

// ---------------------------------------------------------------------------
// Kernel 2: causal sliding-window attention.
// 2 lanes per query: lane owns 32 of 64 dims; partner via shfl.xor(1).
// Packed f32x2 FMA throughout.  Block = 64 queries of one (b,h).
// K/V tiles in smem with +4-float offset for the upper half (bank-disjoint).
// ---------------------------------------------------------------------------
#define QBLK  64
#define KTILE 64
#define ROWST 72    // smem row stride in floats

__global__ __launch_bounds__(128) void attn_kernel(float* __restrict__ out)
{
    __shared__ float Ks[KTILE][ROWST];
    __shared__ float Vs[KTILE][ROWST];

    const int tid   = threadIdx.x;
    const int h     = blockIdx.y;
    const int b     = blockIdx.z;
    const int q0    = blockIdx.x * QBLK;
    const int qi    = q0 + (tid >> 1);          // absolute query index
    const int half  = tid & 1;                  // which 32-dim half
    const int wq    = q0 + (tid >> 5) * 16;     // warp-uniform query base (16 q/warp)

    // load this thread's half of q (already scaled by 1/sqrt(hd))
    unsigned long long q2[16];
    {
        const ulonglong2* qg = (const ulonglong2*)(
            g_q + ((size_t)qi * BATCH + b) * DMODEL + h * HDIM + half * 32);
#pragma unroll
        for (int i = 0; i < 8; i++) {
            ulonglong2 t = qg[i];
            q2[2 * i]     = t.x;
            q2[2 * i + 1] = t.y;
        }
    }

    unsigned long long acc2[16];
#pragma unroll
    for (int i = 0; i < 16; i++) acc2[i] = 0ull;
    float m = -1e30f, l = 0.f;

    const int jstart = q0 - WSZ;   // span QBLK + WSZ = 320 keys = 5 tiles

    for (int t = 0; t < 5; t++) {
        const int j0 = jstart + t * KTILE;
        if (j0 + KTILE <= 0) continue;          // tile fully before sequence
        __syncthreads();
        // cooperative fill (zero out-of-range), upper half shifted +4 floats
#pragma unroll
        for (int it = 0; it < 8; it++) {
            const int f   = tid + 128 * it;
            const int row = f >> 4;
            const int c4  = (f & 15) << 2;
            const int col = c4 + (c4 >= 32 ? 4 : 0);
            const int j   = j0 + row;
            float4 kk4 = make_float4(0.f, 0.f, 0.f, 0.f);
            float4 vv4 = make_float4(0.f, 0.f, 0.f, 0.f);
            if (j >= 0 && j < S_LEN) {
                const size_t base = ((size_t)j * BATCH + b) * DMODEL + h * HDIM + c4;
                kk4 = *(const float4*)(g_k + base);
                vv4 = *(const float4*)(g_v + base);
            }
            *(float4*)&Ks[row][col] = kk4;
            *(float4*)&Vs[row][col] = vv4;
        }
        __syncthreads();

        for (int jj = 0; jj < KTILE; jj++) {
            const int j = j0 + jj;
            // warp-uniform key liveness
            if (j < 0)          continue;
            if (j > wq + 15)    continue;
            if (j < wq - WSZ)   continue;

            // partial dot over own 32 dims (packed)
            unsigned long long s2 = 0ull;
            const ulonglong2* kr = (const ulonglong2*)&Ks[jj][half * 36];
#pragma unroll
            for (int i = 0; i < 8; i++) {
                ulonglong2 kk = kr[i];
                s2 = fma2_(q2[2 * i], kk.x, s2);
                s2 = fma2_(q2[2 * i + 1], kk.y, s2);
            }
            float sx, sy;
            upk2(s2, sx, sy);
            float s = sx + sy;
            s += __shfl_xor_sync(0xffffffffu, s, 1);

            if (j <= qi && j >= qi - WSZ) {
                if (s > m) {                        // lazy rescale (exact)
                    const float sc = __expf(m - s);
                    m = s;
                    l *= sc;
                    const unsigned long long sc2 = pk2(sc, sc);
#pragma unroll
                    for (int i = 0; i < 16; i++) acc2[i] = mul2_(acc2[i], sc2);
                }
                const float p = __expf(s - m);
                l += p;
                const unsigned long long p2 = pk2(p, p);
                const ulonglong2* vr = (const ulonglong2*)&Vs[jj][half * 36];
#pragma unroll
                for (int i = 0; i < 8; i++) {
                    ulonglong2 vv = vr[i];
                    acc2[2 * i]     = fma2_(p2, vv.x, acc2[2 * i]);
                    acc2[2 * i + 1] = fma2_(p2, vv.y, acc2[2 * i + 1]);
                }
            }
        }
    }

    const float inv = 1.f / l;
    float* og = out + ((size_t)qi * BATCH + b) * DMODEL + h * HDIM + half * 32;
#pragma unroll
    for (int i = 0; i < 8; i++) {
        float x0, y0, x1, y1;
        upk2(acc2[2 * i], x0, y0);
        upk2(acc2[2 * i + 1], x1, y1);
        *(float4*)(og + 4 * i) =
            make_float4(x0 * inv, y0 * inv, x1 * inv, y1 * inv);
    }
}

// ---------------------------------------------------------------------------
extern "C" void kernel_launch(void* const* d_in, const int* in_sizes, int n_in,
                              void* d_out, int out_size)
{
    const float* val = (const float*)d_in[0];
    const float* Wq  = (const float*)d_in[1];
    const float* bq  = (const float*)d_in[2];
    const float* Wk  = (const float*)d_in[3];
    const float* bk  = (const float*)d_in[4];
    const float* Wv  = (const float*)d_in[5];
    const float* bv  = (const float*)d_in[6];
    float* out = (float*)d_out;

    dim3 g1(DMODEL / GBN, NROWS / GBM, 3);   // 6 x 64 x 3
    qkv_gemm_tc<<<g1, 128>>>(val, Wq, bq, Wk, bk, Wv, bv);

    dim3 g2(S_LEN / QBLK, NHEAD, BATCH);     // 64 x 12 x 2
    attn_kernel<<<g2, 128>>>(out);
}